// round 7
// baseline (speedup 1.0000x reference)
#include <cuda_runtime.h>
#include <stdint.h>

// fftshift ∘ ifftshift on even dims (320,320): net roll ≡ 0 → identity.
// Output == input bit-for-bit; the task is a 104.86 MB D2D copy.
//
// R2-R5 established that hand-written SM copy kernels (1x and 4x float4,
// .cs hints) all cap at ~5.6 TB/s (70% of spec) on this part. Switch to
// cudaMemcpyAsync: graph-capturable as a memcpy node, dispatched to the
// driver's tuned copy path (CE or optimized SM copy), which sustains
// higher effective HBM bandwidth for large aligned D2D transfers.

extern "C" void kernel_launch(void* const* d_in, const int* in_sizes, int n_in,
                              void* d_out, int out_size) {
    const void* src = d_in[0];
    size_t bytes = (size_t)out_size * sizeof(float);
    cudaMemcpyAsync(d_out, src, bytes, cudaMemcpyDeviceToDevice, 0);
}

// round 8
// speedup vs baseline: 1.0148x; 1.0148x over previous
#include <cuda_runtime.h>
#include <stdint.h>

// fftshift ∘ ifftshift on even dims (320,320): net roll ≡ 0 → identity.
// Task reduces to a 104.86 MB D2D copy.
//
// Established across R1-R6: SM float4 copies (MLP 1 and 4) and the driver
// cudaMemcpyAsync all cap at ~5.6 TB/s DRAM / ~7.5 TB/s combined L2 traffic,
// i.e. the path-independent LTS throughput wall (~6300 B/cyc). 27.8 µs is the
// hardware floor for this read+write stream. This version only trims
// structural overhead: 8 float4/thread, exact-cover grid (3200×256×8 == n4),
// fully unrolled straight-line body, front-batched loads (MLP_p1=8).

__global__ void copy_f4x8_kernel(const float4* __restrict__ src,
                                 float4* __restrict__ dst) {
    const int stride = gridDim.x * blockDim.x;
    const int i = blockIdx.x * blockDim.x + threadIdx.x;

    float4 r0 = __ldcs(src + i);
    float4 r1 = __ldcs(src + i + stride);
    float4 r2 = __ldcs(src + i + 2 * stride);
    float4 r3 = __ldcs(src + i + 3 * stride);
    float4 r4 = __ldcs(src + i + 4 * stride);
    float4 r5 = __ldcs(src + i + 5 * stride);
    float4 r6 = __ldcs(src + i + 6 * stride);
    float4 r7 = __ldcs(src + i + 7 * stride);

    __stcs(dst + i,              r0);
    __stcs(dst + i + stride,     r1);
    __stcs(dst + i + 2 * stride, r2);
    __stcs(dst + i + 3 * stride, r3);
    __stcs(dst + i + 4 * stride, r4);
    __stcs(dst + i + 5 * stride, r5);
    __stcs(dst + i + 6 * stride, r6);
    __stcs(dst + i + 7 * stride, r7);
}

// Generic fallback for sizes not divisible by threads*8 (not hit here).
__global__ void copy_f4_tail_kernel(const float4* __restrict__ src,
                                    float4* __restrict__ dst,
                                    int start, int n4) {
    int i = start + blockIdx.x * blockDim.x + threadIdx.x;
    if (i < n4) dst[i] = src[i];
}

extern "C" void kernel_launch(void* const* d_in, const int* in_sizes, int n_in,
                              void* d_out, int out_size) {
    const float4* src = (const float4*)d_in[0];
    float4* dst = (float4*)d_out;

    int n4 = out_size / 4;  // 6,553,600 for this problem

    const int threads = 256;
    const int per_block = threads * 8;
    int blocks = n4 / per_block;          // 3200: exact cover of 6,553,600
    if (blocks > 0) {
        copy_f4x8_kernel<<<blocks, threads>>>(src, dst);
    }
    int done = blocks * per_block;
    int rem = n4 - done;
    if (rem > 0) {
        copy_f4_tail_kernel<<<(rem + threads - 1) / threads, threads>>>(
            src, dst, done, n4);
    }
}

// round 9
// speedup vs baseline: 1.0466x; 1.0314x over previous
#include <cuda_runtime.h>
#include <stdint.h>

// fftshift ∘ ifftshift on even dims (320,320): net roll ≡ 0 → identity.
// Task is a 104.86 MB D2D copy pinned at the HBM read+write-stream wall
// (~5.6 TB/s, 70% of spec) across all prior SM variants and cudaMemcpyAsync.
//
// R8: Blackwell 256-bit global accesses (ld/st.global.v8.f32, sm_100+) on the
// winning R2 geometry (256 thr × 6400 blocks). 2×32B per thread, evict-first
// on loads. Halves L1tex wavefronts + LSU dispatches per byte vs float4.

struct __align__(32) f32x8 { float v[8]; };

__device__ __forceinline__ f32x8 ldg256_cs(const f32x8* p) {
    f32x8 r;
    asm volatile(
        "ld.global.nc.L1::evict_first.v8.f32 {%0,%1,%2,%3,%4,%5,%6,%7}, [%8];"
        : "=f"(r.v[0]), "=f"(r.v[1]), "=f"(r.v[2]), "=f"(r.v[3]),
          "=f"(r.v[4]), "=f"(r.v[5]), "=f"(r.v[6]), "=f"(r.v[7])
        : "l"(p));
    return r;
}

__device__ __forceinline__ void stg256_cs(f32x8* p, const f32x8& r) {
    asm volatile(
        "st.global.L1::evict_first.v8.f32 [%0], {%1,%2,%3,%4,%5,%6,%7,%8};"
        :: "l"(p),
           "f"(r.v[0]), "f"(r.v[1]), "f"(r.v[2]), "f"(r.v[3]),
           "f"(r.v[4]), "f"(r.v[5]), "f"(r.v[6]), "f"(r.v[7])
        : "memory");
}

__global__ void copy_v8x2_kernel(const f32x8* __restrict__ src,
                                 f32x8* __restrict__ dst) {
    const int stride = gridDim.x * blockDim.x;
    const int i = blockIdx.x * blockDim.x + threadIdx.x;

    f32x8 a = ldg256_cs(src + i);
    f32x8 b = ldg256_cs(src + i + stride);
    stg256_cs(dst + i,          a);
    stg256_cs(dst + i + stride, b);
}

// Fallback tail (not hit for this problem's exact-cover size).
__global__ void copy_f4_tail_kernel(const float4* __restrict__ src,
                                    float4* __restrict__ dst,
                                    int start, int n4) {
    int i = start + blockIdx.x * blockDim.x + threadIdx.x;
    if (i < n4) dst[i] = src[i];
}

extern "C" void kernel_launch(void* const* d_in, const int* in_sizes, int n_in,
                              void* d_out, int out_size) {
    int n4 = out_size / 4;          // float4 count: 6,553,600
    int n8 = n4 / 2;                // f32x8 count:  3,276,800

    const int threads = 256;
    const int per_block = threads * 2;          // f32x8 per block
    int blocks = n8 / per_block;                // 6400: exact cover
    if (blocks > 0) {
        copy_v8x2_kernel<<<blocks, threads>>>((const f32x8*)d_in[0],
                                              (f32x8*)d_out);
    }
    int done4 = blocks * per_block * 2;         // float4s covered
    int rem4 = n4 - done4;
    if (rem4 > 0) {
        copy_f4_tail_kernel<<<(rem4 + threads - 1) / threads, threads>>>(
            (const float4*)d_in[0], (float4*)d_out, done4, n4);
    }
}

// round 10
// speedup vs baseline: 1.0580x; 1.0109x over previous
#include <cuda_runtime.h>
#include <stdint.h>

// fftshift ∘ ifftshift on even dims (320,320): net roll ≡ 0 → identity.
// Task is a 104.86 MB D2D copy. R8 established we are at 7.72 TB/s combined
// DRAM traffic = 96.5% of the 8 TB/s HBM spec (floor = 26.2 µs kernel).
//
// R9 single-variable change vs R8: stores use DEFAULT cache policy (no
// evict_first) so dirty lines buffer in L2 (dst fits in the 126 MB L2) and
// write-back is scheduled behind the compulsory read stream instead of
// eagerly contending with it. Loads stay .nc + evict_first (zero reuse;
// keep L2 capacity for write buffering).

struct __align__(32) f32x8 { float v[8]; };

__device__ __forceinline__ f32x8 ldg256_ef(const f32x8* p) {
    f32x8 r;
    asm volatile(
        "ld.global.nc.L1::evict_first.v8.f32 {%0,%1,%2,%3,%4,%5,%6,%7}, [%8];"
        : "=f"(r.v[0]), "=f"(r.v[1]), "=f"(r.v[2]), "=f"(r.v[3]),
          "=f"(r.v[4]), "=f"(r.v[5]), "=f"(r.v[6]), "=f"(r.v[7])
        : "l"(p));
    return r;
}

__device__ __forceinline__ void stg256(f32x8* p, const f32x8& r) {
    asm volatile(
        "st.global.v8.f32 [%0], {%1,%2,%3,%4,%5,%6,%7,%8};"
        :: "l"(p),
           "f"(r.v[0]), "f"(r.v[1]), "f"(r.v[2]), "f"(r.v[3]),
           "f"(r.v[4]), "f"(r.v[5]), "f"(r.v[6]), "f"(r.v[7])
        : "memory");
}

__global__ void copy_v8x2_kernel(const f32x8* __restrict__ src,
                                 f32x8* __restrict__ dst) {
    const int stride = gridDim.x * blockDim.x;
    const int i = blockIdx.x * blockDim.x + threadIdx.x;

    f32x8 a = ldg256_ef(src + i);
    f32x8 b = ldg256_ef(src + i + stride);
    stg256(dst + i,          a);
    stg256(dst + i + stride, b);
}

// Fallback tail (not hit for this problem's exact-cover size).
__global__ void copy_f4_tail_kernel(const float4* __restrict__ src,
                                    float4* __restrict__ dst,
                                    int start, int n4) {
    int i = start + blockIdx.x * blockDim.x + threadIdx.x;
    if (i < n4) dst[i] = src[i];
}

extern "C" void kernel_launch(void* const* d_in, const int* in_sizes, int n_in,
                              void* d_out, int out_size) {
    int n4 = out_size / 4;          // float4 count: 6,553,600
    int n8 = n4 / 2;                // f32x8 count:  3,276,800

    const int threads = 256;
    const int per_block = threads * 2;          // f32x8 per block
    int blocks = n8 / per_block;                // 6400: exact cover
    if (blocks > 0) {
        copy_v8x2_kernel<<<blocks, threads>>>((const f32x8*)d_in[0],
                                              (f32x8*)d_out);
    }
    int done4 = blocks * per_block * 2;         // float4s covered
    int rem4 = n4 - done4;
    if (rem4 > 0) {
        copy_f4_tail_kernel<<<(rem4 + threads - 1) / threads, threads>>>(
            (const float4*)d_in[0], (float4*)d_out, done4, n4);
    }
}